// round 13
// baseline (speedup 1.0000x reference)
#include <cuda_runtime.h>
#include <cstdint>
#include <cstddef>

#define BB 32
#define SS 64
#define TT 64
#define HH 1024
#define VV 32000
#define G3H 3072
#define NBLK 128
#define KC 128

// ---------------- scratch (device globals; no allocation allowed) ----------------
__device__ float g_Uk[BB * SS * HH];
__device__ float g_X[TT * BB * HH];
__device__ float g_GiX[TT * BB * G3H];      // interleaved cols (3h+g)
__device__ float g_Hall[TT * BB * HH];
__device__ float g_Q[BB * HH];
__device__ float g_GH[BB * G3H];            // interleaved cols (3h+g)
__device__ float g_Ctx[BB * HH];
__device__ float g_Wih2[G3H * 2 * HH];      // W_ih rows interleaved (3h+g)
__device__ float g_Whh2[G3H * HH];          // W_hh rows interleaved
__device__ float g_bih2[G3H];
__device__ float g_bhh2[G3H];
__device__ unsigned g_arrive;

// ---------------- helpers ----------------
typedef unsigned long long ull;
struct __align__(16) ULL2 { ull x, y; };

__device__ __forceinline__ void upk2(ull v, float& lo, float& hi) {
    asm("mov.b64 {%0, %1}, %2;" : "=f"(lo), "=f"(hi) : "l"(v));
}
__device__ __forceinline__ void ffma2(ull& c, ull a, ull b) {
    asm("fma.rn.f32x2 %0, %1, %2, %0;" : "+l"(c) : "l"(a), "l"(b));
}
__device__ __forceinline__ float tanh_ap(float x) {
    float y; asm("tanh.approx.f32 %0, %1;" : "=f"(y) : "f"(x)); return y;
}
__device__ __forceinline__ unsigned ld_acq(unsigned* p) {
    unsigned v;
    asm volatile("ld.acquire.gpu.global.u32 %0, [%1];" : "=r"(v) : "l"(p) : "memory");
    return v;
}
__device__ __forceinline__ void red_rel_add(unsigned* p, unsigned v) {
    asm volatile("red.release.gpu.global.add.u32 [%0], %1;" :: "l"(p), "r"(v) : "memory");
}
__device__ __forceinline__ void gridbar(unsigned target) {
    __syncthreads();
    if (threadIdx.x == 0) {
        red_rel_add(&g_arrive, 1u);
        while (ld_acq(&g_arrive) < target) { }
    }
    __syncthreads();
}
__device__ __forceinline__ unsigned t32(float x) {
    unsigned r; asm("cvt.rna.tf32.f32 %0, %1;" : "=r"(r) : "f"(x)); return r;
}
__device__ __forceinline__ void mma8(float& c0, float& c1, float& c2, float& c3,
                                     unsigned a0, unsigned a1, unsigned a2, unsigned a3,
                                     unsigned b0, unsigned b1) {
    asm volatile(
        "mma.sync.aligned.m16n8k8.row.col.f32.tf32.tf32.f32 "
        "{%0,%1,%2,%3}, {%4,%5,%6,%7}, {%8,%9}, {%0,%1,%2,%3};"
        : "+f"(c0), "+f"(c1), "+f"(c2), "+f"(c3)
        : "r"(a0), "r"(a1), "r"(a2), "r"(a3), "r"(b0), "r"(b1));
}

// =================================================================================
// tf32 tensor-core GEMM (unchanged from 5040us kernel)
// =================================================================================
__global__ __launch_bounds__(256)
void gemmTC(const float* __restrict__ A, int lda,
            const float* __restrict__ W, int ldw,
            const float* __restrict__ bias, float* __restrict__ C, int N, int mode)
{
    __shared__ unsigned As[128][36];
    __shared__ unsigned Ws[128][36];
    const int tid = threadIdx.x;
    const int m0 = blockIdx.x * 128;
    const int n0 = blockIdx.y * 128;
    const int wid = tid >> 5, lane = tid & 31;
    const int gid = lane >> 2, tig = lane & 3;
    const int wm = (wid >> 2) * 64;
    const int wn = (wid & 3) * 32;

    const int lrow = tid >> 1;
    const int lcb = (tid & 1) << 4;
    const float* Arow = A + (size_t)(m0 + lrow) * lda + lcb;
    const float* Wrow = W + (size_t)(n0 + lrow) * ldw + lcb;

    float acc[4][4][4];
#pragma unroll
    for (int i = 0; i < 4; i++)
#pragma unroll
        for (int j = 0; j < 4; j++)
#pragma unroll
            for (int e = 0; e < 4; e++) acc[i][j][e] = 0.f;

    float4 ra[4], rw[4];
#pragma unroll
    for (int j = 0; j < 4; j++) {
        ra[j] = *(const float4*)(Arow + j * 4);
        rw[j] = *(const float4*)(Wrow + j * 4);
    }

    unsigned af[2][4][4], bf[2][4][2];

    for (int ck = 0; ck < HH / 32; ck++) {
        __syncthreads();
#pragma unroll
        for (int j = 0; j < 4; j++) {
            As[lrow][lcb + j * 4 + 0] = t32(ra[j].x);
            As[lrow][lcb + j * 4 + 1] = t32(ra[j].y);
            As[lrow][lcb + j * 4 + 2] = t32(ra[j].z);
            As[lrow][lcb + j * 4 + 3] = t32(ra[j].w);
            Ws[lrow][lcb + j * 4 + 0] = t32(rw[j].x);
            Ws[lrow][lcb + j * 4 + 1] = t32(rw[j].y);
            Ws[lrow][lcb + j * 4 + 2] = t32(rw[j].z);
            Ws[lrow][lcb + j * 4 + 3] = t32(rw[j].w);
        }
        __syncthreads();
        if (ck + 1 < HH / 32) {
            int kt = (ck + 1) * 32;
#pragma unroll
            for (int j = 0; j < 4; j++) {
                ra[j] = *(const float4*)(Arow + kt + j * 4);
                rw[j] = *(const float4*)(Wrow + kt + j * 4);
            }
        }
#pragma unroll
        for (int mf = 0; mf < 4; mf++) {
            int r = wm + mf * 16 + gid;
            af[0][mf][0] = As[r][tig];
            af[0][mf][1] = As[r + 8][tig];
            af[0][mf][2] = As[r][tig + 4];
            af[0][mf][3] = As[r + 8][tig + 4];
        }
#pragma unroll
        for (int nf = 0; nf < 4; nf++) {
            int c = wn + nf * 8 + gid;
            bf[0][nf][0] = Ws[c][tig];
            bf[0][nf][1] = Ws[c][tig + 4];
        }
#pragma unroll
        for (int ks = 0; ks < 4; ks++) {
            const int cur = ks & 1, nxt = cur ^ 1;
            if (ks < 3) {
                const int kk = (ks + 1) * 8;
#pragma unroll
                for (int mf = 0; mf < 4; mf++) {
                    int r = wm + mf * 16 + gid;
                    af[nxt][mf][0] = As[r][kk + tig];
                    af[nxt][mf][1] = As[r + 8][kk + tig];
                    af[nxt][mf][2] = As[r][kk + tig + 4];
                    af[nxt][mf][3] = As[r + 8][kk + tig + 4];
                }
#pragma unroll
                for (int nf = 0; nf < 4; nf++) {
                    int c = wn + nf * 8 + gid;
                    bf[nxt][nf][0] = Ws[c][kk + tig];
                    bf[nxt][nf][1] = Ws[c][kk + tig + 4];
                }
            }
#pragma unroll
            for (int mf = 0; mf < 4; mf++)
#pragma unroll
                for (int nf = 0; nf < 4; nf++)
                    mma8(acc[mf][nf][0], acc[mf][nf][1], acc[mf][nf][2], acc[mf][nf][3],
                         af[cur][mf][0], af[cur][mf][1], af[cur][mf][2], af[cur][mf][3],
                         bf[cur][nf][0], bf[cur][nf][1]);
        }
    }

#pragma unroll
    for (int mf = 0; mf < 4; mf++) {
#pragma unroll
        for (int rr = 0; rr < 2; rr++) {
            int m = m0 + wm + mf * 16 + gid + rr * 8;
            float* crow;
            if (mode == 1) {
                int tt = m >> 5, b = m & 31;
                crow = C + (size_t)b * ((size_t)TT * VV) + (size_t)tt * VV;
            } else {
                crow = C + (size_t)m * N;
            }
#pragma unroll
            for (int nf = 0; nf < 4; nf++) {
                int n = n0 + wn + nf * 8 + tig * 2;
                float2 v;
                v.x = acc[mf][nf][rr * 2 + 0] + bias[n];
                v.y = acc[mf][nf][rr * 2 + 1] + bias[n + 1];
                *(float2*)(crow + n) = v;
            }
        }
    }
}

// ---------------- tile32: C[32 x 32cols] = A[32,1024] @ W^T (unchanged) ----------
__device__ __forceinline__ void tile32(
    float (*As)[132], float (*Ws)[132],
    const float* __restrict__ A, int lda,
    const float* __restrict__ W, int ldw, int n0,
    const float* __restrict__ bias,
    float* __restrict__ C, int ldc, int tid)
{
    const int ml = tid >> 3;
    const int cl = tid & 7;
    const int kb = cl * 4;
    ull acc[4] = {0ull, 0ull, 0ull, 0ull};
    float4 ra[4], rw[4];
    const float* Arow = A + (size_t)ml * lda;
    const float* Wrow = W + (size_t)(n0 + ml) * ldw;

#pragma unroll
    for (int j = 0; j < 4; j++) {
        ra[j] = *(const float4*)(Arow + kb + j * 32);
        rw[j] = *(const float4*)(Wrow + kb + j * 32);
    }
    for (int ck = 0; ck < HH / KC; ck++) {
        __syncthreads();
#pragma unroll
        for (int j = 0; j < 4; j++) {
            *(float4*)&As[ml][kb + j * 32] = ra[j];
            *(float4*)&Ws[ml][kb + j * 32] = rw[j];
        }
        __syncthreads();
        if (ck + 1 < HH / KC) {
            int kc = (ck + 1) * KC;
#pragma unroll
            for (int j = 0; j < 4; j++) {
                ra[j] = *(const float4*)(Arow + kc + kb + j * 32);
                rw[j] = *(const float4*)(Wrow + kc + kb + j * 32);
            }
        }
#pragma unroll 16
        for (int k = 0; k < KC; k += 4) {
            ULL2 a = *(const ULL2*)&As[ml][k];
#pragma unroll
            for (int j = 0; j < 4; j++) {
                ULL2 w = *(const ULL2*)&Ws[cl + j * 8][k];
                ffma2(acc[j], a.x, w.x);
                ffma2(acc[j], a.y, w.y);
            }
        }
    }
#pragma unroll
    for (int j = 0; j < 4; j++) {
        float lo, hi;
        upk2(acc[j], lo, hi);
        int n = n0 + cl + j * 8;
        C[(size_t)ml * ldc + n] = lo + hi + bias[n];
    }
}

// ---------------- tile48: Gs[32][48cols] = A[32,1024] @ W^T + init (smem out) ----
__device__ __forceinline__ void tile48(
    float (*As)[132], float (*Ws)[132], float (*Gs)[49],
    const float* __restrict__ A, int lda,
    const float* __restrict__ W, int ldw, int n0,
    const float* __restrict__ init, int ldi, int tid)
{
    const int ml = tid >> 3;
    const int cl = tid & 7;
    const int kb = cl * 4;
    ull acc[6] = {0ull, 0ull, 0ull, 0ull, 0ull, 0ull};
    float4 ra[4], rw0[4], rw1[4];
    const float* Arow = A + (size_t)ml * lda;
    const int wr0 = tid >> 3, ws0 = (tid & 7) << 4;           // i0 = tid  (<256)
    const int i1 = tid + 256;                                  // second W slice
    const int wr1 = i1 >> 3, ws1 = (i1 & 7) << 4;              // valid if i1<384
    const float* W0 = W + (size_t)(n0 + wr0) * ldw + ws0;
    const float* W1 = W + (size_t)(n0 + (i1 < 384 ? wr1 : 0)) * ldw + ws1;

#pragma unroll
    for (int j = 0; j < 4; j++) ra[j] = *(const float4*)(Arow + kb + j * 32);
#pragma unroll
    for (int j = 0; j < 4; j++) rw0[j] = *(const float4*)(W0 + j * 4);
    if (i1 < 384)
#pragma unroll
        for (int j = 0; j < 4; j++) rw1[j] = *(const float4*)(W1 + j * 4);

    for (int ck = 0; ck < HH / KC; ck++) {
        __syncthreads();
#pragma unroll
        for (int j = 0; j < 4; j++) *(float4*)&As[ml][kb + j * 32] = ra[j];
#pragma unroll
        for (int j = 0; j < 4; j++) *(float4*)&Ws[wr0][ws0 + j * 4] = rw0[j];
        if (i1 < 384)
#pragma unroll
            for (int j = 0; j < 4; j++) *(float4*)&Ws[wr1][ws1 + j * 4] = rw1[j];
        __syncthreads();
        if (ck + 1 < HH / KC) {
            const int kc = (ck + 1) * KC;
#pragma unroll
            for (int j = 0; j < 4; j++) ra[j] = *(const float4*)(Arow + kc + kb + j * 32);
#pragma unroll
            for (int j = 0; j < 4; j++) rw0[j] = *(const float4*)(W0 + kc + j * 4);
            if (i1 < 384)
#pragma unroll
                for (int j = 0; j < 4; j++) rw1[j] = *(const float4*)(W1 + kc + j * 4);
        }
#pragma unroll 16
        for (int k = 0; k < KC; k += 4) {
            ULL2 a = *(const ULL2*)&As[ml][k];
#pragma unroll
            for (int j = 0; j < 6; j++) {
                ULL2 w = *(const ULL2*)&Ws[cl + j * 8][k];
                ffma2(acc[j], a.x, w.x);
                ffma2(acc[j], a.y, w.y);
            }
        }
    }
#pragma unroll
    for (int j = 0; j < 6; j++) {
        float lo, hi;
        upk2(acc[j], lo, hi);
        int n = cl + j * 8;
        Gs[ml][n] = lo + hi + init[(size_t)ml * ldi + n0 + n];
    }
}

// ---------------- persistent recurrence: 3 global phases per step ----------------
__global__ __launch_bounds__(256, 1)
void recur(const float* __restrict__ h0, const float* __restrict__ enc,
           const float* __restrict__ Wa_w, const float* __restrict__ Wa_b,
           const float* __restrict__ Va_w, const float* __restrict__ Va_b,
           float* __restrict__ attn_out, float* __restrict__ hT_out)
{
    // 48512-byte smem union (fits 48K static limit)
    __shared__ float S[12128];
    float (*As)[132] = (float (*)[132])S;                  // 4224 floats
    float (*Ws)[132] = (float (*)[132])(S + 4224);         // up to 48 rows (6336)
    float (*Gs)[49]  = (float (*)[49])(S + 4224 + 6336);   // 1568 floats
    float* smq  = S;                                       // B-phase aliases
    float* smva = S + 1024;
    float* smsc = S + 2048;
    float* smex = S + 2112;

    const int blk = blockIdx.x;
    const int tid = threadIdx.x;
    unsigned bt = 0;

    for (int t = 0; t < TT; t++) {
        const float* hid = (t == 0) ? h0 : (g_Hall + (size_t)(t - 1) * BB * HH);

        // ---- phase A: q (blk<32) + interleaved GH (blk 32..127) ----
        if (blk < 32)
            tile32(As, Ws, hid, HH, Wa_w, HH, blk * 32, Wa_b, g_Q, HH, tid);
        else
            tile32(As, Ws, hid, HH, g_Whh2, HH, (blk - 32) * 32, g_bhh2,
                   g_GH, G3H, tid);
        bt += NBLK; gridbar(bt);

        // ---- phase B: scores + softmax + attn write + context (32 fat blocks) ----
        if (blk < 32) {
            const int b = blk;
            for (int i = tid; i < HH; i += 256) {
                smq[i] = g_Q[b * HH + i];
                smva[i] = Va_w[i];
            }
            __syncthreads();
            const int w = tid >> 5, lane = tid & 31;
#pragma unroll
            for (int si = 0; si < 8; si++) {
                const int s = w * 8 + si;
                const float* uk = g_Uk + (size_t)(b * SS + s) * HH;
                float sum = 0.f;
#pragma unroll 8
                for (int h = lane; h < HH; h += 32)
                    sum += smva[h] * tanh_ap(smq[h] + uk[h]);
#pragma unroll
                for (int o = 16; o; o >>= 1)
                    sum += __shfl_xor_sync(0xffffffffu, sum, o);
                if (lane == 0) smsc[s] = sum + Va_b[0];
            }
            __syncthreads();
            if (tid < 32) {
                float a = smsc[tid], c = smsc[tid + 32];
                float mx = fmaxf(a, c);
#pragma unroll
                for (int o = 16; o; o >>= 1)
                    mx = fmaxf(mx, __shfl_xor_sync(0xffffffffu, mx, o));
                float e0 = expf(a - mx), e1 = expf(c - mx);
                float sm = e0 + e1;
#pragma unroll
                for (int o = 16; o; o >>= 1)
                    sm += __shfl_xor_sync(0xffffffffu, sm, o);
                float inv = 1.f / sm;
                smex[tid] = e0 * inv;
                smex[tid + 32] = e1 * inv;
                attn_out[(size_t)b * TT * SS + (size_t)t * SS + tid] = e0 * inv;
                attn_out[(size_t)b * TT * SS + (size_t)t * SS + tid + 32] = e1 * inv;
            }
            __syncthreads();
#pragma unroll
            for (int k = 0; k < 4; k++) {
                const int h = tid + k * 256;
                const float* eb = enc + (size_t)b * SS * HH + h;
                float acc = 0.f;
#pragma unroll 8
                for (int s = 0; s < SS; s++) acc += smex[s] * eb[(size_t)s * HH];
                g_Ctx[b * HH + h] = acc;
            }
        }
        bt += NBLK; gridbar(bt);

        // ---- phase C': gi tile (interleaved) in smem + inline GRU (64 blocks) ----
        if (blk < 64) {
            tile48(As, Ws, Gs, g_Ctx, HH, g_Wih2 + HH, 2 * HH, blk * 48,
                   g_GiX + (size_t)t * BB * G3H, G3H, tid);
            __syncthreads();
#pragma unroll
            for (int k = 0; k < 2; k++) {
                const int idx = tid + k * 256;       // 512 slots = 32b x 16h
                const int b = idx >> 4, dh = idx & 15;
                const int h = blk * 16 + dh;
                const float ir = Gs[b][3 * dh], iz = Gs[b][3 * dh + 1],
                            in_ = Gs[b][3 * dh + 2];
                const int gb = b * G3H + blk * 48 + 3 * dh;
                const float hr = g_GH[gb], hz = g_GH[gb + 1], hn = g_GH[gb + 2];
                float r = 1.f / (1.f + expf(-(ir + hr)));
                float z = 1.f / (1.f + expf(-(iz + hz)));
                float nv = tanhf(in_ + r * hn);
                float hnew = (1.f - z) * nv + z * hid[b * HH + h];
                g_Hall[(size_t)t * BB * HH + b * HH + h] = hnew;
                if (t == TT - 1) hT_out[b * HH + h] = hnew;
            }
        }
        bt += NBLK; gridbar(bt);
    }
}

// phase 0: interleave GRU weight rows to 3h+g order (exact permutation)
__global__ __launch_bounds__(256)
void shuffle_w(const float* __restrict__ Wih, const float* __restrict__ bih,
               const float* __restrict__ Whh, const float* __restrict__ bhh)
{
    const int row = blockIdx.x;          // 0..3071 dest (interleaved) row
    const int g = row % 3, h = row / 3;
    const int src = g * HH + h;
    const int tid = threadIdx.x;
    const float4* s1 = (const float4*)(Wih + (size_t)src * 2 * HH);
    float4* d1 = (float4*)(g_Wih2 + (size_t)row * 2 * HH);
    d1[tid] = s1[tid];
    d1[tid + 256] = s1[tid + 256];       // 512 float4 = 2048 floats
    const float4* s2 = (const float4*)(Whh + (size_t)src * HH);
    float4* d2 = (float4*)(g_Whh2 + (size_t)row * HH);
    d2[tid] = s2[tid];                   // 256 float4 = 1024 floats
    if (tid == 0) {
        g_bih2[row] = bih[src];
        g_bhh2[row] = bhh[src];
    }
}

// tokens: tok(b,0)=SOS=1, tok(b,t)=target[b,t-1]; gather emb rows; reset barrier
__global__ __launch_bounds__(256)
void gather_emb(const int* __restrict__ target, const float* __restrict__ emb)
{
    if (blockIdx.x == 0 && threadIdx.x == 0) g_arrive = 0;
    const int r = blockIdx.x;
    const int t = r >> 5, b = r & 31;
    const int tok = (t == 0) ? 1 : target[b * TT + (t - 1)];
    const float4* src = (const float4*)(emb + (size_t)tok * HH);
    float4* dst = (float4*)(g_X + (size_t)r * HH);
    dst[threadIdx.x] = src[threadIdx.x];
}

extern "C" void kernel_launch(void* const* d_in, const int* in_sizes, int n_in,
                              void* d_out, int out_size)
{
    (void)in_sizes; (void)n_in; (void)out_size;
    const float* enc   = (const float*)d_in[0];
    const float* h0    = (const float*)d_in[1];
    const int*   tgt   = (const int*)d_in[2];
    const float* emb   = (const float*)d_in[3];
    const float* Wa_w  = (const float*)d_in[4];
    const float* Wa_b  = (const float*)d_in[5];
    const float* Ua_w  = (const float*)d_in[6];
    const float* Ua_b  = (const float*)d_in[7];
    const float* Va_w  = (const float*)d_in[8];
    const float* Va_b  = (const float*)d_in[9];
    const float* W_ih  = (const float*)d_in[10];
    const float* W_hh  = (const float*)d_in[11];
    const float* b_ih  = (const float*)d_in[12];
    const float* b_hh  = (const float*)d_in[13];
    const float* out_w = (const float*)d_in[14];
    const float* out_b = (const float*)d_in[15];

    float* out = (float*)d_out;
    float* dec_out  = out;                                          // B*T*V
    float* hT_out   = out + (size_t)BB * TT * VV;                   // B*H
    float* attn_out = out + (size_t)BB * TT * VV + (size_t)BB * HH; // B*T*S

    float *Uk, *X, *GiX, *Hall, *Wih2, *bih2;
    cudaGetSymbolAddress((void**)&Uk, g_Uk);
    cudaGetSymbolAddress((void**)&X, g_X);
    cudaGetSymbolAddress((void**)&GiX, g_GiX);
    cudaGetSymbolAddress((void**)&Hall, g_Hall);
    cudaGetSymbolAddress((void**)&Wih2, g_Wih2);
    cudaGetSymbolAddress((void**)&bih2, g_bih2);

    // Phase 0: barrier reset + token gather + weight interleave + invariant GEMMs
    gather_emb<<<TT * BB, 256>>>(tgt, emb);
    shuffle_w<<<G3H, 256>>>(W_ih, b_ih, W_hh, b_hh);
    gemmTC<<<dim3((BB * SS) / 128, HH / 128), 256>>>(enc, HH, Ua_w, HH, Ua_b, Uk, HH, 0);
    // GiX (interleaved cols) = X @ Wih2[:, :H]^T + bih2
    gemmTC<<<dim3((TT * BB) / 128, G3H / 128), 256>>>(X, HH, Wih2, 2 * HH, bih2, GiX, G3H, 0);

    // Phase 1: persistent fused recurrence (3 grid barriers per step)
    recur<<<NBLK, 256>>>(h0, enc, Wa_w, Wa_b, Va_w, Va_b, attn_out, hT_out);

    // Phase 2: batched vocab projection (tensor cores, tf32)
    gemmTC<<<dim3((TT * BB) / 128, VV / 128), 256>>>(Hall, HH, out_w, HH, out_b,
                                                     dec_out, VV, 1);
}

// round 14
// speedup vs baseline: 1.5714x; 1.5714x over previous
#include <cuda_runtime.h>
#include <cstdint>
#include <cstddef>

#define BB 32
#define SS 64
#define TT 64
#define HH 1024
#define VV 32000
#define G3H 3072
#define NBLK 128
#define KC 128

// ---------------- scratch (device globals; no allocation allowed) ----------------
__device__ float g_Uk[BB * SS * HH];
__device__ float g_X[TT * BB * HH];
__device__ float g_GiX[TT * BB * G3H];
__device__ float g_Hall[TT * BB * HH];
__device__ float g_Q[BB * HH];
__device__ float g_GH[BB * G3H];
__device__ float g_GI[BB * G3H];
__device__ float g_Ctx[BB * HH];
__device__ float g_Sc[BB * SS];
__device__ unsigned g_arrive;

// ---------------- helpers ----------------
__device__ __forceinline__ float tanh_ap(float x) {
    float y; asm("tanh.approx.f32 %0, %1;" : "=f"(y) : "f"(x)); return y;
}
__device__ __forceinline__ unsigned ld_acq(unsigned* p) {
    unsigned v;
    asm volatile("ld.acquire.gpu.global.u32 %0, [%1];" : "=r"(v) : "l"(p) : "memory");
    return v;
}
__device__ __forceinline__ void red_rel_add(unsigned* p, unsigned v) {
    asm volatile("red.release.gpu.global.add.u32 [%0], %1;" :: "l"(p), "r"(v) : "memory");
}
__device__ __forceinline__ void gridbar(unsigned target) {
    __syncthreads();
    if (threadIdx.x == 0) {
        red_rel_add(&g_arrive, 1u);
        while (ld_acq(&g_arrive) < target) { }
    }
    __syncthreads();
}
__device__ __forceinline__ unsigned t32(float x) {
    unsigned r; asm("cvt.rna.tf32.f32 %0, %1;" : "=r"(r) : "f"(x)); return r;
}
__device__ __forceinline__ void mma8(float& c0, float& c1, float& c2, float& c3,
                                     unsigned a0, unsigned a1, unsigned a2, unsigned a3,
                                     unsigned b0, unsigned b1) {
    asm volatile(
        "mma.sync.aligned.m16n8k8.row.col.f32.tf32.tf32.f32 "
        "{%0,%1,%2,%3}, {%4,%5,%6,%7}, {%8,%9}, {%0,%1,%2,%3};"
        : "+f"(c0), "+f"(c1), "+f"(c2), "+f"(c3)
        : "r"(a0), "r"(a1), "r"(a2), "r"(a3), "r"(b0), "r"(b1));
}

// =================================================================================
// tf32 tensor-core GEMM (unchanged, proven): C = A[M,1024]*W^T + bias
// =================================================================================
__global__ __launch_bounds__(256)
void gemmTC(const float* __restrict__ A, int lda,
            const float* __restrict__ W, int ldw,
            const float* __restrict__ bias, float* __restrict__ C, int N, int mode)
{
    __shared__ unsigned As[128][36];
    __shared__ unsigned Ws[128][36];
    const int tid = threadIdx.x;
    const int m0 = blockIdx.x * 128;
    const int n0 = blockIdx.y * 128;
    const int wid = tid >> 5, lane = tid & 31;
    const int gid = lane >> 2, tig = lane & 3;
    const int wm = (wid >> 2) * 64;
    const int wn = (wid & 3) * 32;

    const int lrow = tid >> 1;
    const int lcb = (tid & 1) << 4;
    const float* Arow = A + (size_t)(m0 + lrow) * lda + lcb;
    const float* Wrow = W + (size_t)(n0 + lrow) * ldw + lcb;

    float acc[4][4][4];
#pragma unroll
    for (int i = 0; i < 4; i++)
#pragma unroll
        for (int j = 0; j < 4; j++)
#pragma unroll
            for (int e = 0; e < 4; e++) acc[i][j][e] = 0.f;

    float4 ra[4], rw[4];
#pragma unroll
    for (int j = 0; j < 4; j++) {
        ra[j] = *(const float4*)(Arow + j * 4);
        rw[j] = *(const float4*)(Wrow + j * 4);
    }

    unsigned af[2][4][4], bf[2][4][2];

    for (int ck = 0; ck < HH / 32; ck++) {
        __syncthreads();
#pragma unroll
        for (int j = 0; j < 4; j++) {
            As[lrow][lcb + j * 4 + 0] = t32(ra[j].x);
            As[lrow][lcb + j * 4 + 1] = t32(ra[j].y);
            As[lrow][lcb + j * 4 + 2] = t32(ra[j].z);
            As[lrow][lcb + j * 4 + 3] = t32(ra[j].w);
            Ws[lrow][lcb + j * 4 + 0] = t32(rw[j].x);
            Ws[lrow][lcb + j * 4 + 1] = t32(rw[j].y);
            Ws[lrow][lcb + j * 4 + 2] = t32(rw[j].z);
            Ws[lrow][lcb + j * 4 + 3] = t32(rw[j].w);
        }
        __syncthreads();
        if (ck + 1 < HH / 32) {
            int kt = (ck + 1) * 32;
#pragma unroll
            for (int j = 0; j < 4; j++) {
                ra[j] = *(const float4*)(Arow + kt + j * 4);
                rw[j] = *(const float4*)(Wrow + kt + j * 4);
            }
        }
#pragma unroll
        for (int mf = 0; mf < 4; mf++) {
            int r = wm + mf * 16 + gid;
            af[0][mf][0] = As[r][tig];
            af[0][mf][1] = As[r + 8][tig];
            af[0][mf][2] = As[r][tig + 4];
            af[0][mf][3] = As[r + 8][tig + 4];
        }
#pragma unroll
        for (int nf = 0; nf < 4; nf++) {
            int c = wn + nf * 8 + gid;
            bf[0][nf][0] = Ws[c][tig];
            bf[0][nf][1] = Ws[c][tig + 4];
        }
#pragma unroll
        for (int ks = 0; ks < 4; ks++) {
            const int cur = ks & 1, nxt = cur ^ 1;
            if (ks < 3) {
                const int kk = (ks + 1) * 8;
#pragma unroll
                for (int mf = 0; mf < 4; mf++) {
                    int r = wm + mf * 16 + gid;
                    af[nxt][mf][0] = As[r][kk + tig];
                    af[nxt][mf][1] = As[r + 8][kk + tig];
                    af[nxt][mf][2] = As[r][kk + tig + 4];
                    af[nxt][mf][3] = As[r + 8][kk + tig + 4];
                }
#pragma unroll
                for (int nf = 0; nf < 4; nf++) {
                    int c = wn + nf * 8 + gid;
                    bf[nxt][nf][0] = Ws[c][kk + tig];
                    bf[nxt][nf][1] = Ws[c][kk + tig + 4];
                }
            }
#pragma unroll
            for (int mf = 0; mf < 4; mf++)
#pragma unroll
                for (int nf = 0; nf < 4; nf++)
                    mma8(acc[mf][nf][0], acc[mf][nf][1], acc[mf][nf][2], acc[mf][nf][3],
                         af[cur][mf][0], af[cur][mf][1], af[cur][mf][2], af[cur][mf][3],
                         bf[cur][nf][0], bf[cur][nf][1]);
        }
    }

#pragma unroll
    for (int mf = 0; mf < 4; mf++) {
#pragma unroll
        for (int rr = 0; rr < 2; rr++) {
            int m = m0 + wm + mf * 16 + gid + rr * 8;
            float* crow;
            if (mode == 1) {
                int tt = m >> 5, b = m & 31;
                crow = C + (size_t)b * ((size_t)TT * VV) + (size_t)tt * VV;
            } else {
                crow = C + (size_t)m * N;
            }
#pragma unroll
            for (int nf = 0; nf < 4; nf++) {
                int n = n0 + wn + nf * 8 + tig * 2;
                float2 v;
                v.x = acc[mf][nf][rr * 2 + 0] + bias[n];
                v.y = acc[mf][nf][rr * 2 + 1] + bias[n + 1];
                *(float2*)(crow + n) = v;
            }
        }
    }
}

// =================================================================================
// mtile32: C[32 x 32] = A[32,1024] @ W[n0:n0+32, :]^T (+bias, +init) — tensor cores
// 256 thr = 8 warps (2m x 4n), warp = m16 x n8, K-chunks of 128, m16n8k8 tf32.
// Fragment mapping identical to gemmTC (proven). [132] padding: conflict-free.
// =================================================================================
__device__ __forceinline__ void mtile32(
    unsigned (*As)[132], unsigned (*Ws)[132],
    const float* __restrict__ A, int lda,
    const float* __restrict__ W, int ldw, int n0,
    const float* __restrict__ bias,
    const float* __restrict__ init, int ldi,
    float* __restrict__ C, int ldc, int tid)
{
    const int wid = tid >> 5, lane = tid & 31;
    const int gid = lane >> 2, tig = lane & 3;
    const int wm = (wid >> 2) * 16;      // 0 or 16
    const int wn = (wid & 3) * 8;        // 0,8,16,24
    const int lr = tid >> 3;             // loader row 0..31
    const int lc = (tid & 7) * 16;       // loader col base 0..112

    float4 ra[4], rw[4];
    const float* Arow = A + (size_t)lr * lda + lc;
    const float* Wrow = W + (size_t)(n0 + lr) * ldw + lc;
#pragma unroll
    for (int j = 0; j < 4; j++) {
        ra[j] = *(const float4*)(Arow + j * 4);
        rw[j] = *(const float4*)(Wrow + j * 4);
    }
    float acc[4] = {0.f, 0.f, 0.f, 0.f};

    for (int ck = 0; ck < HH / KC; ck++) {
        __syncthreads();
#pragma unroll
        for (int j = 0; j < 4; j++) {
            uint4 av = make_uint4(t32(ra[j].x), t32(ra[j].y), t32(ra[j].z), t32(ra[j].w));
            uint4 wv = make_uint4(t32(rw[j].x), t32(rw[j].y), t32(rw[j].z), t32(rw[j].w));
            *(uint4*)&As[lr][lc + j * 4] = av;
            *(uint4*)&Ws[lr][lc + j * 4] = wv;
        }
        __syncthreads();
        if (ck + 1 < HH / KC) {
            const int kc = (ck + 1) * KC;
#pragma unroll
            for (int j = 0; j < 4; j++) {
                ra[j] = *(const float4*)(Arow + kc + j * 4);
                rw[j] = *(const float4*)(Wrow + kc + j * 4);
            }
        }
#pragma unroll
        for (int kk = 0; kk < KC; kk += 8) {
            unsigned a0 = As[wm + gid][kk + tig];
            unsigned a1 = As[wm + gid + 8][kk + tig];
            unsigned a2 = As[wm + gid][kk + tig + 4];
            unsigned a3 = As[wm + gid + 8][kk + tig + 4];
            unsigned b0 = Ws[wn + gid][kk + tig];
            unsigned b1 = Ws[wn + gid][kk + tig + 4];
            mma8(acc[0], acc[1], acc[2], acc[3], a0, a1, a2, a3, b0, b1);
        }
    }
    // epilogue: lane owns rows wm+gid, wm+gid+8; cols wn + 2*tig, +1
#pragma unroll
    for (int rr = 0; rr < 2; rr++) {
        const int m = wm + gid + rr * 8;
#pragma unroll
        for (int cc = 0; cc < 2; cc++) {
            const int nn = n0 + wn + tig * 2 + cc;
            float v = acc[rr * 2 + cc];
            if (bias) v += bias[nn];
            if (init) v += init[(size_t)m * ldi + nn];
            C[(size_t)m * ldc + nn] = v;
        }
    }
}

// ---------------- persistent recurrence: round-10 5-phase structure -------------
__global__ __launch_bounds__(256, 1)
void recur(const float* __restrict__ h0, const float* __restrict__ enc,
           const float* __restrict__ Wa_w, const float* __restrict__ Wa_b,
           const float* __restrict__ W_hh, const float* __restrict__ b_hh,
           const float* __restrict__ W_ih,
           const float* __restrict__ Va_w, const float* __restrict__ Va_b,
           float* __restrict__ attn_out, float* __restrict__ hT_out)
{
    __shared__ unsigned As[32][132];
    __shared__ unsigned Ws[32][132];
    __shared__ float smq[HH];
    __shared__ float smva[HH];
    __shared__ float smsc[SS];
    __shared__ float smex[SS];

    const int blk = blockIdx.x;
    const int tid = threadIdx.x;
    unsigned bt = 0;

    for (int t = 0; t < TT; t++) {
        const float* hid = (t == 0) ? h0 : (g_Hall + (size_t)(t - 1) * BB * HH);

        // phase A: q (tasks 0..31) + GH (tasks 32..127) — tensor-core tiles
        if (blk < 32)
            mtile32(As, Ws, hid, HH, Wa_w, HH, blk * 32, Wa_b,
                    nullptr, 0, g_Q, HH, tid);
        else
            mtile32(As, Ws, hid, HH, W_hh, HH, (blk - 32) * 32, b_hh,
                    nullptr, 0, g_GH, G3H, tid);
        bt += NBLK; gridbar(bt);

        // phase B1: scores[b][s] = Va . tanh(q[b] + Uk[b,s]) + Va_b
        {
            const int b = blk >> 2, sg = (blk & 3) * 16;
            for (int i = tid; i < HH; i += 256) {
                smq[i] = g_Q[b * HH + i];
                smva[i] = Va_w[i];
            }
            __syncthreads();
            const int w = tid >> 5, lane = tid & 31;
#pragma unroll
            for (int si = 0; si < 2; si++) {
                int s = sg + w * 2 + si;
                const float* uk = g_Uk + (size_t)(b * SS + s) * HH;
                float sum = 0.f;
#pragma unroll 8
                for (int h = lane; h < HH; h += 32)
                    sum += smva[h] * tanh_ap(smq[h] + uk[h]);
#pragma unroll
                for (int o = 16; o; o >>= 1)
                    sum += __shfl_xor_sync(0xffffffffu, sum, o);
                if (lane == 0) g_Sc[b * SS + s] = sum + Va_b[0];
            }
        }
        bt += NBLK; gridbar(bt);

        // phase B2: softmax + attentions output + context (h-quartered)
        {
            const int b = blk >> 2, hq = blk & 3;
            if (tid < SS) smsc[tid] = g_Sc[b * SS + tid];
            __syncthreads();
            float mx = -1e30f;
#pragma unroll
            for (int s = 0; s < SS; s++) mx = fmaxf(mx, smsc[s]);
            if (tid < SS) smex[tid] = expf(smsc[tid] - mx);
            __syncthreads();
            float sum = 0.f;
#pragma unroll
            for (int s = 0; s < SS; s++) sum += smex[s];
            const float inv = 1.f / sum;
            const int h = hq * 256 + tid;
            const float* eb = enc + (size_t)b * SS * HH + h;
            float acc = 0.f;
#pragma unroll 8
            for (int s = 0; s < SS; s++) acc += smex[s] * eb[(size_t)s * HH];
            g_Ctx[b * HH + h] = acc * inv;
            if (hq == 0 && tid < SS)
                attn_out[(size_t)b * TT * SS + (size_t)t * SS + tid] = smex[tid] * inv;
        }
        bt += NBLK; gridbar(bt);

        // phase C: GI = GiX[t] + ctx @ W_ih[:, H:]^T   (96 tile tasks)
        if (blk < 96) {
            mtile32(As, Ws, g_Ctx, HH, W_ih + HH, 2 * HH, blk * 32, nullptr,
                    g_GiX + (size_t)t * BB * G3H, G3H, g_GI, G3H, tid);
        }
        bt += NBLK; gridbar(bt);

        // phase D: GRU combine (PyTorch semantics)
        if (blk < 32) {
            const int b = blk;
            for (int h = tid; h < HH; h += 256) {
                float ir = g_GI[b * G3H + h],           hr = g_GH[b * G3H + h];
                float iz = g_GI[b * G3H + HH + h],      hz = g_GH[b * G3H + HH + h];
                float in_ = g_GI[b * G3H + 2 * HH + h], hn = g_GH[b * G3H + 2 * HH + h];
                float r = 1.f / (1.f + expf(-(ir + hr)));
                float z = 1.f / (1.f + expf(-(iz + hz)));
                float nv = tanhf(in_ + r * hn);
                float hnew = (1.f - z) * nv + z * hid[b * HH + h];
                g_Hall[(size_t)t * BB * HH + b * HH + h] = hnew;
                if (t == TT - 1) hT_out[b * HH + h] = hnew;
            }
        }
        bt += NBLK; gridbar(bt);
    }
}

// tokens: tok(b,0)=SOS=1, tok(b,t)=target[b,t-1]; gather emb rows; reset barrier
__global__ __launch_bounds__(256)
void gather_emb(const int* __restrict__ target, const float* __restrict__ emb)
{
    if (blockIdx.x == 0 && threadIdx.x == 0) g_arrive = 0;
    const int r = blockIdx.x;
    const int t = r >> 5, b = r & 31;
    const int tok = (t == 0) ? 1 : target[b * TT + (t - 1)];
    const float4* src = (const float4*)(emb + (size_t)tok * HH);
    float4* dst = (float4*)(g_X + (size_t)r * HH);
    dst[threadIdx.x] = src[threadIdx.x];
}

extern "C" void kernel_launch(void* const* d_in, const int* in_sizes, int n_in,
                              void* d_out, int out_size)
{
    (void)in_sizes; (void)n_in; (void)out_size;
    const float* enc   = (const float*)d_in[0];
    const float* h0    = (const float*)d_in[1];
    const int*   tgt   = (const int*)d_in[2];
    const float* emb   = (const float*)d_in[3];
    const float* Wa_w  = (const float*)d_in[4];
    const float* Wa_b  = (const float*)d_in[5];
    const float* Ua_w  = (const float*)d_in[6];
    const float* Ua_b  = (const float*)d_in[7];
    const float* Va_w  = (const float*)d_in[8];
    const float* Va_b  = (const float*)d_in[9];
    const float* W_ih  = (const float*)d_in[10];
    const float* W_hh  = (const float*)d_in[11];
    const float* b_ih  = (const float*)d_in[12];
    const float* b_hh  = (const float*)d_in[13];
    const float* out_w = (const float*)d_in[14];
    const float* out_b = (const float*)d_in[15];

    float* out = (float*)d_out;
    float* dec_out  = out;                                          // B*T*V
    float* hT_out   = out + (size_t)BB * TT * VV;                   // B*H
    float* attn_out = out + (size_t)BB * TT * VV + (size_t)BB * HH; // B*T*S

    float *Uk, *X, *GiX, *Hall;
    cudaGetSymbolAddress((void**)&Uk, g_Uk);
    cudaGetSymbolAddress((void**)&X, g_X);
    cudaGetSymbolAddress((void**)&GiX, g_GiX);
    cudaGetSymbolAddress((void**)&Hall, g_Hall);

    // Phase 0: barrier reset + token gather + loop-invariant GEMMs
    gather_emb<<<TT * BB, 256>>>(tgt, emb);
    gemmTC<<<dim3((BB * SS) / 128, HH / 128), 256>>>(enc, HH, Ua_w, HH, Ua_b, Uk, HH, 0);
    gemmTC<<<dim3((TT * BB) / 128, G3H / 128), 256>>>(X, HH, W_ih, 2 * HH, b_ih, GiX, G3H, 0);

    // Phase 1: persistent fused recurrence (5 phases/step, tensor-core tiles)
    recur<<<NBLK, 256>>>(h0, enc, Wa_w, Wa_b, W_hh, b_hh, W_ih, Va_w, Va_b,
                         attn_out, hT_out);

    // Phase 2: batched vocab projection (tensor cores, tf32)
    gemmTC<<<dim3((TT * BB) / 128, VV / 128), 256>>>(Hall, HH, out_w, HH, out_b,
                                                     dec_out, VV, 1);
}

// round 15
// speedup vs baseline: 1.6606x; 1.0567x over previous
#include <cuda_runtime.h>
#include <cstdint>
#include <cstddef>

#define BB 32
#define SS 64
#define TT 64
#define HH 1024
#define VV 32000
#define G3H 3072
#define NBLK 128
#define KC 128

// ---------------- scratch (device globals; no allocation allowed) ----------------
__device__ float g_Uk[BB * SS * HH];
__device__ float g_X[TT * BB * HH];
__device__ float g_GiX[TT * BB * G3H];
__device__ float g_Hall[TT * BB * HH];
__device__ float g_Q[BB * HH];
__device__ float g_GH[BB * G3H];
__device__ float g_GI[BB * G3H];
__device__ float g_Ctx[BB * HH];
__device__ float g_Sc[BB * SS];
__device__ unsigned g_arrive;

// ---------------- helpers ----------------
__device__ __forceinline__ float tanh_ap(float x) {
    float y; asm("tanh.approx.f32 %0, %1;" : "=f"(y) : "f"(x)); return y;
}
__device__ __forceinline__ unsigned ld_acq(unsigned* p) {
    unsigned v;
    asm volatile("ld.acquire.gpu.global.u32 %0, [%1];" : "=r"(v) : "l"(p) : "memory");
    return v;
}
__device__ __forceinline__ void red_rel_add(unsigned* p, unsigned v) {
    asm volatile("red.release.gpu.global.add.u32 [%0], %1;" :: "l"(p), "r"(v) : "memory");
}
__device__ __forceinline__ void gridbar(unsigned target) {
    __syncthreads();
    if (threadIdx.x == 0) {
        red_rel_add(&g_arrive, 1u);
        while (ld_acq(&g_arrive) < target) { }
    }
    __syncthreads();
}
__device__ __forceinline__ unsigned t32(float x) {
    unsigned r; asm("cvt.rna.tf32.f32 %0, %1;" : "=r"(r) : "f"(x)); return r;
}
__device__ __forceinline__ void mma8(float& c0, float& c1, float& c2, float& c3,
                                     unsigned a0, unsigned a1, unsigned a2, unsigned a3,
                                     unsigned b0, unsigned b1) {
    asm volatile(
        "mma.sync.aligned.m16n8k8.row.col.f32.tf32.tf32.f32 "
        "{%0,%1,%2,%3}, {%4,%5,%6,%7}, {%8,%9}, {%0,%1,%2,%3};"
        : "+f"(c0), "+f"(c1), "+f"(c2), "+f"(c3)
        : "r"(a0), "r"(a1), "r"(a2), "r"(a3), "r"(b0), "r"(b1));
}
// ldmatrix: 4 / 2 8x8-b16 tiles (= 8x4 b32); lane->(row=l>>2&7grp, col=l&3) matches tf32 frags
__device__ __forceinline__ void ldsm4(unsigned& r0, unsigned& r1, unsigned& r2,
                                      unsigned& r3, unsigned addr) {
    asm volatile("ldmatrix.sync.aligned.m8n8.x4.shared.b16 {%0,%1,%2,%3}, [%4];"
                 : "=r"(r0), "=r"(r1), "=r"(r2), "=r"(r3) : "r"(addr));
}
__device__ __forceinline__ void ldsm2(unsigned& r0, unsigned& r1, unsigned addr) {
    asm volatile("ldmatrix.sync.aligned.m8n8.x2.shared.b16 {%0,%1}, [%2];"
                 : "=r"(r0), "=r"(r1) : "r"(addr));
}
__device__ __forceinline__ unsigned smem_u32(const void* p) {
    return (unsigned)__cvta_generic_to_shared(p);
}

// =================================================================================
// tf32 tensor-core GEMM: C[M,N] = A[M,1024]*W[N,ldw]^T + bias — LDSM fragment loads
// block 128x128, 256 thr = 8 warps (2m x 4n), warp 64x32, K-chunk 32.
// mode 0: C row-major ld=N.  mode 1: logits remap row r=t*32+b -> C[b][t*VV + n].
// =================================================================================
__global__ __launch_bounds__(256)
void gemmTC(const float* __restrict__ A, int lda,
            const float* __restrict__ W, int ldw,
            const float* __restrict__ bias, float* __restrict__ C, int N, int mode)
{
    __shared__ unsigned As[128][36];
    __shared__ unsigned Ws[128][36];
    const int tid = threadIdx.x;
    const int m0 = blockIdx.x * 128;
    const int n0 = blockIdx.y * 128;
    const int wid = tid >> 5, lane = tid & 31;
    const int gid = lane >> 2, tig = lane & 3;
    const int wm = (wid >> 2) * 64;
    const int wn = (wid & 3) * 32;

    // LDSM per-lane address bases (byte addresses). j = lane>>3 selects sub-matrix.
    const int j = lane >> 3, rsel = lane & 7;
    unsigned aAddr[4], bAddr[2];
#pragma unroll
    for (int mf = 0; mf < 4; mf++)
        aAddr[mf] = smem_u32(&As[wm + mf * 16 + (j & 1) * 8 + rsel][(j >> 1) * 4]);
#pragma unroll
    for (int nfp = 0; nfp < 2; nfp++)
        bAddr[nfp] = smem_u32(&Ws[wn + (2 * nfp + (j >> 1)) * 8 + rsel][(j & 1) * 4]);

    const int lrow = tid >> 1;
    const int lcb = (tid & 1) << 4;
    const float* Arow = A + (size_t)(m0 + lrow) * lda + lcb;
    const float* Wrow = W + (size_t)(n0 + lrow) * ldw + lcb;

    float acc[4][4][4];
#pragma unroll
    for (int i = 0; i < 4; i++)
#pragma unroll
        for (int jj = 0; jj < 4; jj++)
#pragma unroll
            for (int e = 0; e < 4; e++) acc[i][jj][e] = 0.f;

    float4 ra[4], rw[4];
#pragma unroll
    for (int jj = 0; jj < 4; jj++) {
        ra[jj] = *(const float4*)(Arow + jj * 4);
        rw[jj] = *(const float4*)(Wrow + jj * 4);
    }

    for (int ck = 0; ck < HH / 32; ck++) {
        __syncthreads();
#pragma unroll
        for (int jj = 0; jj < 4; jj++) {
            As[lrow][lcb + jj * 4 + 0] = t32(ra[jj].x);
            As[lrow][lcb + jj * 4 + 1] = t32(ra[jj].y);
            As[lrow][lcb + jj * 4 + 2] = t32(ra[jj].z);
            As[lrow][lcb + jj * 4 + 3] = t32(ra[jj].w);
            Ws[lrow][lcb + jj * 4 + 0] = t32(rw[jj].x);
            Ws[lrow][lcb + jj * 4 + 1] = t32(rw[jj].y);
            Ws[lrow][lcb + jj * 4 + 2] = t32(rw[jj].z);
            Ws[lrow][lcb + jj * 4 + 3] = t32(rw[jj].w);
        }
        __syncthreads();
        if (ck + 1 < HH / 32) {
            int kt = (ck + 1) * 32;
#pragma unroll
            for (int jj = 0; jj < 4; jj++) {
                ra[jj] = *(const float4*)(Arow + kt + jj * 4);
                rw[jj] = *(const float4*)(Wrow + kt + jj * 4);
            }
        }
#pragma unroll
        for (int ks = 0; ks < 4; ks++) {
            const unsigned ko = ks * 32;           // kk * 4 bytes
            unsigned af[4][4], bf[4][2];
#pragma unroll
            for (int mf = 0; mf < 4; mf++)
                ldsm4(af[mf][0], af[mf][1], af[mf][2], af[mf][3], aAddr[mf] + ko);
#pragma unroll
            for (int nfp = 0; nfp < 2; nfp++)
                ldsm4(bf[2 * nfp][0], bf[2 * nfp][1],
                      bf[2 * nfp + 1][0], bf[2 * nfp + 1][1], bAddr[nfp] + ko);
#pragma unroll
            for (int mf = 0; mf < 4; mf++)
#pragma unroll
                for (int nf = 0; nf < 4; nf++)
                    mma8(acc[mf][nf][0], acc[mf][nf][1], acc[mf][nf][2], acc[mf][nf][3],
                         af[mf][0], af[mf][1], af[mf][2], af[mf][3],
                         bf[nf][0], bf[nf][1]);
        }
    }

#pragma unroll
    for (int mf = 0; mf < 4; mf++) {
#pragma unroll
        for (int rr = 0; rr < 2; rr++) {
            int m = m0 + wm + mf * 16 + gid + rr * 8;
            float* crow;
            if (mode == 1) {
                int tt = m >> 5, b = m & 31;
                crow = C + (size_t)b * ((size_t)TT * VV) + (size_t)tt * VV;
            } else {
                crow = C + (size_t)m * N;
            }
#pragma unroll
            for (int nf = 0; nf < 4; nf++) {
                int n = n0 + wn + nf * 8 + tig * 2;
                float2 v;
                v.x = acc[mf][nf][rr * 2 + 0] + bias[n];
                v.y = acc[mf][nf][rr * 2 + 1] + bias[n + 1];
                *(float2*)(crow + n) = v;
            }
        }
    }
}

// =================================================================================
// mtile32: C[32 x 32] = A[32,1024] @ W[n0:n0+32, :]^T (+bias, +init) — LDSM loads
// 256 thr = 8 warps (2m x 4n), warp = m16 x n8, K-chunks of 128, m16n8k8 tf32.
// =================================================================================
__device__ __forceinline__ void mtile32(
    unsigned (*As)[132], unsigned (*Ws)[132],
    const float* __restrict__ A, int lda,
    const float* __restrict__ W, int ldw, int n0,
    const float* __restrict__ bias,
    const float* __restrict__ init, int ldi,
    float* __restrict__ C, int ldc, int tid)
{
    const int wid = tid >> 5, lane = tid & 31;
    const int gid = lane >> 2, tig = lane & 3;
    const int wm = (wid >> 2) * 16;      // 0 or 16
    const int wn = (wid & 3) * 8;        // 0,8,16,24
    const int lr = tid >> 3;             // loader row 0..31
    const int lc = (tid & 7) * 16;       // loader col base 0..112

    // LDSM lane addresses
    const int j = lane >> 3, rsel = lane & 7;
    const unsigned aAddr = smem_u32(&As[wm + (j & 1) * 8 + rsel][(j >> 1) * 4]);
    const int j2 = (lane & 15) >> 3;     // x2 uses lanes 0..15
    const unsigned bAddr = smem_u32(&Ws[wn + (lane & 7)][j2 * 4]);

    float4 ra[4], rw[4];
    const float* Arow = A + (size_t)lr * lda + lc;
    const float* Wrow = W + (size_t)(n0 + lr) * ldw + lc;
#pragma unroll
    for (int jj = 0; jj < 4; jj++) {
        ra[jj] = *(const float4*)(Arow + jj * 4);
        rw[jj] = *(const float4*)(Wrow + jj * 4);
    }
    float acc[4] = {0.f, 0.f, 0.f, 0.f};

    for (int ck = 0; ck < HH / KC; ck++) {
        __syncthreads();
#pragma unroll
        for (int jj = 0; jj < 4; jj++) {
            uint4 av = make_uint4(t32(ra[jj].x), t32(ra[jj].y), t32(ra[jj].z), t32(ra[jj].w));
            uint4 wv = make_uint4(t32(rw[jj].x), t32(rw[jj].y), t32(rw[jj].z), t32(rw[jj].w));
            *(uint4*)&As[lr][lc + jj * 4] = av;
            *(uint4*)&Ws[lr][lc + jj * 4] = wv;
        }
        __syncthreads();
        if (ck + 1 < HH / KC) {
            const int kc = (ck + 1) * KC;
#pragma unroll
            for (int jj = 0; jj < 4; jj++) {
                ra[jj] = *(const float4*)(Arow + kc + jj * 4);
                rw[jj] = *(const float4*)(Wrow + kc + jj * 4);
            }
        }
#pragma unroll
        for (int kk = 0; kk < KC; kk += 8) {
            const unsigned ko = kk * 4;
            unsigned a0, a1, a2, a3, b0, b1;
            ldsm4(a0, a1, a2, a3, aAddr + ko);
            ldsm2(b0, b1, bAddr + ko);
            mma8(acc[0], acc[1], acc[2], acc[3], a0, a1, a2, a3, b0, b1);
        }
    }
    // epilogue: lane owns rows wm+gid, wm+gid+8; cols wn + 2*tig, +1
#pragma unroll
    for (int rr = 0; rr < 2; rr++) {
        const int m = wm + gid + rr * 8;
#pragma unroll
        for (int cc = 0; cc < 2; cc++) {
            const int nn = n0 + wn + tig * 2 + cc;
            float v = acc[rr * 2 + cc];
            if (bias) v += bias[nn];
            if (init) v += init[(size_t)m * ldi + nn];
            C[(size_t)m * ldc + nn] = v;
        }
    }
}

// ---------------- persistent recurrence: 5-phase structure (proven) --------------
__global__ __launch_bounds__(256, 1)
void recur(const float* __restrict__ h0, const float* __restrict__ enc,
           const float* __restrict__ Wa_w, const float* __restrict__ Wa_b,
           const float* __restrict__ W_hh, const float* __restrict__ b_hh,
           const float* __restrict__ W_ih,
           const float* __restrict__ Va_w, const float* __restrict__ Va_b,
           float* __restrict__ attn_out, float* __restrict__ hT_out)
{
    __shared__ unsigned As[32][132];
    __shared__ unsigned Ws[32][132];
    __shared__ float smq[HH];
    __shared__ float smva[HH];
    __shared__ float smsc[SS];
    __shared__ float smex[SS];

    const int blk = blockIdx.x;
    const int tid = threadIdx.x;
    unsigned bt = 0;

    for (int t = 0; t < TT; t++) {
        const float* hid = (t == 0) ? h0 : (g_Hall + (size_t)(t - 1) * BB * HH);

        // phase A: q (tasks 0..31) + GH (tasks 32..127)
        if (blk < 32)
            mtile32(As, Ws, hid, HH, Wa_w, HH, blk * 32, Wa_b,
                    nullptr, 0, g_Q, HH, tid);
        else
            mtile32(As, Ws, hid, HH, W_hh, HH, (blk - 32) * 32, b_hh,
                    nullptr, 0, g_GH, G3H, tid);
        bt += NBLK; gridbar(bt);

        // phase B1: scores[b][s] = Va . tanh(q[b] + Uk[b,s]) + Va_b
        {
            const int b = blk >> 2, sg = (blk & 3) * 16;
            for (int i = tid; i < HH; i += 256) {
                smq[i] = g_Q[b * HH + i];
                smva[i] = Va_w[i];
            }
            __syncthreads();
            const int w = tid >> 5, lane = tid & 31;
#pragma unroll
            for (int si = 0; si < 2; si++) {
                int s = sg + w * 2 + si;
                const float* uk = g_Uk + (size_t)(b * SS + s) * HH;
                float sum = 0.f;
#pragma unroll 8
                for (int h = lane; h < HH; h += 32)
                    sum += smva[h] * tanh_ap(smq[h] + uk[h]);
#pragma unroll
                for (int o = 16; o; o >>= 1)
                    sum += __shfl_xor_sync(0xffffffffu, sum, o);
                if (lane == 0) g_Sc[b * SS + s] = sum + Va_b[0];
            }
        }
        bt += NBLK; gridbar(bt);

        // phase B2: softmax + attentions output + context (h-quartered)
        {
            const int b = blk >> 2, hq = blk & 3;
            if (tid < SS) smsc[tid] = g_Sc[b * SS + tid];
            __syncthreads();
            float mx = -1e30f;
#pragma unroll
            for (int s = 0; s < SS; s++) mx = fmaxf(mx, smsc[s]);
            if (tid < SS) smex[tid] = expf(smsc[tid] - mx);
            __syncthreads();
            float sum = 0.f;
#pragma unroll
            for (int s = 0; s < SS; s++) sum += smex[s];
            const float inv = 1.f / sum;
            const int h = hq * 256 + tid;
            const float* eb = enc + (size_t)b * SS * HH + h;
            float acc = 0.f;
#pragma unroll 8
            for (int s = 0; s < SS; s++) acc += smex[s] * eb[(size_t)s * HH];
            g_Ctx[b * HH + h] = acc * inv;
            if (hq == 0 && tid < SS)
                attn_out[(size_t)b * TT * SS + (size_t)t * SS + tid] = smex[tid] * inv;
        }
        bt += NBLK; gridbar(bt);

        // phase C: GI = GiX[t] + ctx @ W_ih[:, H:]^T   (96 tile tasks)
        if (blk < 96) {
            mtile32(As, Ws, g_Ctx, HH, W_ih + HH, 2 * HH, blk * 32, nullptr,
                    g_GiX + (size_t)t * BB * G3H, G3H, g_GI, G3H, tid);
        }
        bt += NBLK; gridbar(bt);

        // phase D: GRU combine (PyTorch semantics)
        if (blk < 32) {
            const int b = blk;
            for (int h = tid; h < HH; h += 256) {
                float ir = g_GI[b * G3H + h],           hr = g_GH[b * G3H + h];
                float iz = g_GI[b * G3H + HH + h],      hz = g_GH[b * G3H + HH + h];
                float in_ = g_GI[b * G3H + 2 * HH + h], hn = g_GH[b * G3H + 2 * HH + h];
                float r = 1.f / (1.f + expf(-(ir + hr)));
                float z = 1.f / (1.f + expf(-(iz + hz)));
                float nv = tanhf(in_ + r * hn);
                float hnew = (1.f - z) * nv + z * hid[b * HH + h];
                g_Hall[(size_t)t * BB * HH + b * HH + h] = hnew;
                if (t == TT - 1) hT_out[b * HH + h] = hnew;
            }
        }
        bt += NBLK; gridbar(bt);
    }
}

// tokens: tok(b,0)=SOS=1, tok(b,t)=target[b,t-1]; gather emb rows; reset barrier
__global__ __launch_bounds__(256)
void gather_emb(const int* __restrict__ target, const float* __restrict__ emb)
{
    if (blockIdx.x == 0 && threadIdx.x == 0) g_arrive = 0;
    const int r = blockIdx.x;
    const int t = r >> 5, b = r & 31;
    const int tok = (t == 0) ? 1 : target[b * TT + (t - 1)];
    const float4* src = (const float4*)(emb + (size_t)tok * HH);
    float4* dst = (float4*)(g_X + (size_t)r * HH);
    dst[threadIdx.x] = src[threadIdx.x];
}

extern "C" void kernel_launch(void* const* d_in, const int* in_sizes, int n_in,
                              void* d_out, int out_size)
{
    (void)in_sizes; (void)n_in; (void)out_size;
    const float* enc   = (const float*)d_in[0];
    const float* h0    = (const float*)d_in[1];
    const int*   tgt   = (const int*)d_in[2];
    const float* emb   = (const float*)d_in[3];
    const float* Wa_w  = (const float*)d_in[4];
    const float* Wa_b  = (const float*)d_in[5];
    const float* Ua_w  = (const float*)d_in[6];
    const float* Ua_b  = (const float*)d_in[7];
    const float* Va_w  = (const float*)d_in[8];
    const float* Va_b  = (const float*)d_in[9];
    const float* W_ih  = (const float*)d_in[10];
    const float* W_hh  = (const float*)d_in[11];
    const float* b_ih  = (const float*)d_in[12];
    const float* b_hh  = (const float*)d_in[13];
    const float* out_w = (const float*)d_in[14];
    const float* out_b = (const float*)d_in[15];

    float* out = (float*)d_out;
    float* dec_out  = out;                                          // B*T*V
    float* hT_out   = out + (size_t)BB * TT * VV;                   // B*H
    float* attn_out = out + (size_t)BB * TT * VV + (size_t)BB * HH; // B*T*S

    float *Uk, *X, *GiX, *Hall;
    cudaGetSymbolAddress((void**)&Uk, g_Uk);
    cudaGetSymbolAddress((void**)&X, g_X);
    cudaGetSymbolAddress((void**)&GiX, g_GiX);
    cudaGetSymbolAddress((void**)&Hall, g_Hall);

    // Phase 0: barrier reset + token gather + loop-invariant GEMMs
    gather_emb<<<TT * BB, 256>>>(tgt, emb);
    gemmTC<<<dim3((BB * SS) / 128, HH / 128), 256>>>(enc, HH, Ua_w, HH, Ua_b, Uk, HH, 0);
    gemmTC<<<dim3((TT * BB) / 128, G3H / 128), 256>>>(X, HH, W_ih, 2 * HH, b_ih, GiX, G3H, 0);

    // Phase 1: persistent fused recurrence (5 phases/step, tensor-core tiles)
    recur<<<NBLK, 256>>>(h0, enc, Wa_w, Wa_b, W_hh, b_hh, W_ih, Va_w, Va_b,
                         attn_out, hT_out);

    // Phase 2: batched vocab projection (tensor cores, tf32)
    gemmTC<<<dim3((TT * BB) / 128, VV / 128), 256>>>(Hall, HH, out_w, HH, out_b,
                                                     dec_out, VV, 1);
}